// round 7
// baseline (speedup 1.0000x reference)
#include <cuda_runtime.h>
#include <math.h>

#define NT   32
#define NJ   7
#define DT_C 0.1f
#define ACT_R 50.0f
#define MAXV 20.0f

struct SC {
    float A[NJ][6];
    float nAw[NJ];
    float G[NJ][36];
    float MR[NJ + 1][9];
    float Mp[NJ + 1][3];
    float MiR[NJ][9];
    float Mip[NJ][3];
    float AeR[9];
    float AeQ[9];
    float g[3];
    float ftip[6];
};

__device__ __forceinline__ void mm33(const float* A, const float* B, float* C) {
#pragma unroll
    for (int r = 0; r < 3; r++)
#pragma unroll
        for (int c = 0; c < 3; c++)
            C[r * 3 + c] = A[r * 3 + 0] * B[0 * 3 + c] + A[r * 3 + 1] * B[1 * 3 + c] + A[r * 3 + 2] * B[2 * 3 + c];
}
__device__ __forceinline__ void mm33_tn(const float* A, const float* B, float* C) {  // A^T * B
#pragma unroll
    for (int r = 0; r < 3; r++)
#pragma unroll
        for (int c = 0; c < 3; c++)
            C[r * 3 + c] = A[0 * 3 + r] * B[0 * 3 + c] + A[1 * 3 + r] * B[1 * 3 + c] + A[2 * 3 + r] * B[2 * 3 + c];
}
__device__ __forceinline__ void mv33(const float* A, const float* x, float* y) {
#pragma unroll
    for (int r = 0; r < 3; r++) y[r] = A[r * 3 + 0] * x[0] + A[r * 3 + 1] * x[1] + A[r * 3 + 2] * x[2];
}
__device__ __forceinline__ void mv33_t(const float* A, const float* x, float* y) {
#pragma unroll
    for (int r = 0; r < 3; r++) y[r] = A[0 * 3 + r] * x[0] + A[1 * 3 + r] * x[1] + A[2 * 3 + r] * x[2];
}
__device__ __forceinline__ void cross3(const float* a, const float* b, float* c) {
    c[0] = a[1] * b[2] - a[2] * b[1];
    c[1] = a[2] * b[0] - a[0] * b[2];
    c[2] = a[0] * b[1] - a[1] * b[0];
}
// R = I + alpha*K + beta*(w w^T - th2*I), K = skew(w)
__device__ __forceinline__ void rodr(float* R, float a, float b, const float* w, float th2) {
    R[0] = 1.f + b * (w[0] * w[0] - th2);
    R[1] = b * w[0] * w[1] - a * w[2];
    R[2] = b * w[0] * w[2] + a * w[1];
    R[3] = b * w[0] * w[1] + a * w[2];
    R[4] = 1.f + b * (w[1] * w[1] - th2);
    R[5] = b * w[1] * w[2] - a * w[0];
    R[6] = b * w[0] * w[2] - a * w[1];
    R[7] = b * w[1] * w[2] + a * w[0];
    R[8] = 1.f + b * (w[2] * w[2] - th2);
}
__device__ __forceinline__ void abc_coeffs(float th, float& a, float& b, float& c) {
    float th2 = th * th;
    if (th < 1e-4f) {
        a = 1.f - th2 * (1.f / 6.f);
        b = 0.5f - th2 * (1.f / 24.f);
        c = (1.f / 6.f) - th2 * (1.f / 120.f);
    } else {
        float sn = sinf(th), co = cosf(th);
        float it = 1.f / th;
        a = sn * it;
        b = (1.f - co) * (it * it);
        c = (th - sn) * (it * it * it);
    }
}

__global__ void __launch_bounds__(NT) arm_kernel(
    const float* __restrict__ state, const float* __restrict__ torque,
    const float* __restrict__ Mg, const float* __restrict__ Ag,
    const float* __restrict__ Lg, const float* __restrict__ gg,
    const float* __restrict__ fg, float* __restrict__ out, int n) {
    __shared__ SC sc;
    __shared__ float sRt[NJ * 9 * NT];
    __shared__ float sQt[NJ * 9 * NT];
    __shared__ float sVs[NJ * 6 * NT];
    __shared__ float sVd[NJ * 6 * NT];

    const int tid = threadIdx.x;

#define SRT(i, k) sRt[((i) * 9 + (k)) * NT + tid]
#define SQT(i, k) sQt[((i) * 9 + (k)) * NT + tid]
#define SVS(i, k) sVs[((i) * 6 + (k)) * NT + tid]
#define SVD(i, k) sVd[((i) * 6 + (k)) * NT + tid]

    // ---- block-shared constant preprocessing ----
    for (int idx = tid; idx < NJ * 6; idx += NT) ((float*)sc.A)[idx] = Ag[idx];
    for (int i = tid; i < NJ; i += NT) {
        float a0 = Ag[i * 6], a1 = Ag[i * 6 + 1], a2 = Ag[i * 6 + 2];
        sc.nAw[i] = sqrtf(a0 * a0 + a1 * a1 + a2 * a2);
    }
    for (int idx = tid; idx < NJ * 36; idx += NT) {
        int i = idx / 36, rc = idx % 36, r = rc / 6, cc = rc % 6;
        const float* Lr = Lg + i * 36 + r * 6;
        const float* Lc = Lg + i * 36 + cc * 6;
        float s = 0.f;
#pragma unroll
        for (int k = 0; k < 6; k++) s += Lr[k] * Lc[k];
        sc.G[i][rc] = s;
    }
    for (int i = tid; i < NJ + 1; i += NT) {
        const float* m = Mg + i * 16;
#pragma unroll
        for (int r = 0; r < 3; r++) {
#pragma unroll
            for (int c = 0; c < 3; c++) sc.MR[i][r * 3 + c] = m[r * 4 + c];
            sc.Mp[i][r] = m[r * 4 + 3];
        }
        if (i < NJ) {
#pragma unroll
            for (int r = 0; r < 3; r++) {
#pragma unroll
                for (int c = 0; c < 3; c++) sc.MiR[i][r * 3 + c] = m[c * 4 + r];
                sc.Mip[i][r] = -(m[0 * 4 + r] * m[0 * 4 + 3] + m[1 * 4 + r] * m[1 * 4 + 3] + m[2 * 4 + r] * m[2 * 4 + 3]);
            }
        }
    }
    if (tid == 0) {
        const float* m = Mg + NJ * 16;
        float Re[9], pe[3];
#pragma unroll
        for (int r = 0; r < 3; r++) {
#pragma unroll
            for (int c = 0; c < 3; c++) Re[r * 3 + c] = m[c * 4 + r];
            pe[r] = -(m[0 * 4 + r] * m[0 * 4 + 3] + m[1 * 4 + r] * m[1 * 4 + 3] + m[2 * 4 + r] * m[2 * 4 + 3]);
        }
#pragma unroll
        for (int c = 0; c < 3; c++) {
            sc.AeQ[0 * 3 + c] = -pe[2] * Re[1 * 3 + c] + pe[1] * Re[2 * 3 + c];
            sc.AeQ[1 * 3 + c] = pe[2] * Re[0 * 3 + c] - pe[0] * Re[2 * 3 + c];
            sc.AeQ[2 * 3 + c] = -pe[1] * Re[0 * 3 + c] + pe[0] * Re[1 * 3 + c];
        }
#pragma unroll
        for (int k = 0; k < 9; k++) sc.AeR[k] = Re[k];
#pragma unroll
        for (int k = 0; k < 3; k++) sc.g[k] = gg[k];
#pragma unroll
        for (int k = 0; k < 6; k++) sc.ftip[k] = fg[k];
    }
    __syncthreads();

    const int b = blockIdx.x * NT + tid;
    if (b >= n) return;

    float q0[NJ], dq0[NJ], tv[NJ];
#pragma unroll
    for (int i = 0; i < NJ; i++) {
        q0[i] = state[b * 14 + i];
        dq0[i] = state[b * 14 + 7 + i];
        tv[i] = torque[b * 7 + i] * ACT_R;
    }
    float qs[NJ], ds[NJ], aq[NJ], ad[NJ];
#pragma unroll
    for (int i = 0; i < NJ; i++) { qs[i] = q0[i]; ds[i] = dq0[i]; aq[i] = 0.f; ad[i] = 0.f; }

    float dd[NJ];

#pragma unroll 1
    for (int st = 0; st < 4; ++st) {
        // ===== forward dynamics: dd = M(q)^-1 (tau - h(q,dq)) =====

        // --- 1. joint adjoints AdT_i = Ad( exp(-A_i q_i) * Minv_i ) as (R, Q=skew(p)R) ---
#pragma unroll 1
        for (int i = 0; i < NJ; i++) {
            float qi = qs[i];
            float Aw[3] = {sc.A[i][0], sc.A[i][1], sc.A[i][2]};
            float Av[3] = {sc.A[i][3], sc.A[i][4], sc.A[i][5]};
            float w[3] = {-Aw[0] * qi, -Aw[1] * qi, -Aw[2] * qi};
            float v[3] = {-Av[0] * qi, -Av[1] * qi, -Av[2] * qi};
            float th = sc.nAw[i] * fabsf(qi);
            float th2 = th * th;
            float a, bb, cc;
            abc_coeffs(th, a, bb, cc);
            float R[9], Vmx[9];
            rodr(R, a, bb, w, th2);
            rodr(Vmx, bb, cc, w, th2);
            float p[3];
            mv33(Vmx, v, p);
            float RT[9];
            mm33(R, sc.MiR[i], RT);
            float pm[3];
            mv33(R, sc.Mip[i], pm);
            float pT[3] = {pm[0] + p[0], pm[1] + p[1], pm[2] + p[2]};
            float Q[9];
#pragma unroll
            for (int c = 0; c < 3; c++) {
                Q[0 * 3 + c] = -pT[2] * RT[1 * 3 + c] + pT[1] * RT[2 * 3 + c];
                Q[1 * 3 + c] = pT[2] * RT[0 * 3 + c] - pT[0] * RT[2 * 3 + c];
                Q[2 * 3 + c] = -pT[1] * RT[0 * 3 + c] + pT[0] * RT[1 * 3 + c];
            }
#pragma unroll
            for (int k = 0; k < 9; k++) { SRT(i, k) = RT[k]; SQT(i, k) = Q[k]; }
        }

        // --- 2. forward recursion (twists / accelerations), ddq = 0, gravity on ---
        {
            float Vw[3] = {0.f, 0.f, 0.f}, Vv[3] = {0.f, 0.f, 0.f};
            float Dw[3] = {0.f, 0.f, 0.f}, Dv[3] = {-sc.g[0], -sc.g[1], -sc.g[2]};
#pragma unroll 1
            for (int i = 0; i < NJ; i++) {
                float R[9], Q[9];
#pragma unroll
                for (int k = 0; k < 9; k++) { R[k] = SRT(i, k); Q[k] = SQT(i, k); }
                float Aw[3] = {sc.A[i][0], sc.A[i][1], sc.A[i][2]};
                float Av[3] = {sc.A[i][3], sc.A[i][4], sc.A[i][5]};
                float dqi = ds[i];
                float t1[3], t2[3], t3[3];
                mv33(R, Vw, t1);
                mv33(Q, Vw, t2);
                mv33(R, Vv, t3);
#pragma unroll
                for (int k = 0; k < 3; k++) { Vw[k] = t1[k] + Aw[k] * dqi; Vv[k] = t2[k] + t3[k] + Av[k] * dqi; }
                mv33(R, Dw, t1);
                mv33(Q, Dw, t2);
                mv33(R, Dv, t3);
                float c1[3], c2[3], c3[3];
                cross3(Vw, Aw, c1);
                cross3(Vv, Aw, c2);
                cross3(Vw, Av, c3);
#pragma unroll
                for (int k = 0; k < 3; k++) {
                    Dw[k] = t1[k] + c1[k] * dqi;
                    Dv[k] = t2[k] + t3[k] + (c2[k] + c3[k]) * dqi;
                }
#pragma unroll
                for (int k = 0; k < 3; k++) {
                    SVS(i, k) = Vw[k]; SVS(i, k + 3) = Vv[k];
                    SVD(i, k) = Dw[k]; SVD(i, k + 3) = Dv[k];
                }
            }
        }

        // --- 3. backward recursion -> bias torques h ---
        float hh[NJ];
        {
            float Fw[3], Fv[3];
            {
                float fw[3] = {sc.ftip[0], sc.ftip[1], sc.ftip[2]};
                float fv[3] = {sc.ftip[3], sc.ftip[4], sc.ftip[5]};
                float t1[3], t2[3], t3[3];
                mv33_t(sc.AeR, fw, t1);
                mv33_t(sc.AeQ, fv, t2);
                mv33_t(sc.AeR, fv, t3);
#pragma unroll
                for (int k = 0; k < 3; k++) { Fw[k] = t1[k] + t2[k]; Fv[k] = t3[k]; }
            }
#pragma unroll 1
            for (int i = NJ - 1; i >= 0; i--) {
                float vw[3], vv[3], dw[3], dv[3];
#pragma unroll
                for (int k = 0; k < 3; k++) {
                    vw[k] = SVS(i, k); vv[k] = SVS(i, k + 3);
                    dw[k] = SVD(i, k); dv[k] = SVD(i, k + 3);
                }
                const float* Gi = sc.G[i];
                float GVw[3], GVv[3], GDw[3], GDv[3];
#pragma unroll
                for (int r = 0; r < 3; r++) {
                    GVw[r] = Gi[r * 6 + 0] * vw[0] + Gi[r * 6 + 1] * vw[1] + Gi[r * 6 + 2] * vw[2] +
                             Gi[r * 6 + 3] * vv[0] + Gi[r * 6 + 4] * vv[1] + Gi[r * 6 + 5] * vv[2];
                    GVv[r] = Gi[(r + 3) * 6 + 0] * vw[0] + Gi[(r + 3) * 6 + 1] * vw[1] + Gi[(r + 3) * 6 + 2] * vw[2] +
                             Gi[(r + 3) * 6 + 3] * vv[0] + Gi[(r + 3) * 6 + 4] * vv[1] + Gi[(r + 3) * 6 + 5] * vv[2];
                    GDw[r] = Gi[r * 6 + 0] * dw[0] + Gi[r * 6 + 1] * dw[1] + Gi[r * 6 + 2] * dw[2] +
                             Gi[r * 6 + 3] * dv[0] + Gi[r * 6 + 4] * dv[1] + Gi[r * 6 + 5] * dv[2];
                    GDv[r] = Gi[(r + 3) * 6 + 0] * dw[0] + Gi[(r + 3) * 6 + 1] * dw[1] + Gi[(r + 3) * 6 + 2] * dw[2] +
                             Gi[(r + 3) * 6 + 3] * dv[0] + Gi[(r + 3) * 6 + 4] * dv[1] + Gi[(r + 3) * 6 + 5] * dv[2];
                }
                float cw[3], cv[3], cx[3];
                cross3(vw, GVw, cw);
                cross3(vv, GVv, cv);
                cross3(vw, GVv, cx);
#pragma unroll
                for (int k = 0; k < 3; k++) {
                    Fw[k] += GDw[k] + cw[k] + cv[k];
                    Fv[k] += GDv[k] + cx[k];
                }
                hh[i] = Fw[0] * sc.A[i][0] + Fw[1] * sc.A[i][1] + Fw[2] * sc.A[i][2] +
                        Fv[0] * sc.A[i][3] + Fv[1] * sc.A[i][4] + Fv[2] * sc.A[i][5];
                if (i > 0) {
                    float R[9], Q[9];
#pragma unroll
                    for (int k = 0; k < 9; k++) { R[k] = SRT(i, k); Q[k] = SQT(i, k); }
                    float t1[3], t2[3], t3[3];
                    mv33_t(R, Fw, t1);
                    mv33_t(Q, Fv, t2);
                    mv33_t(R, Fv, t3);
#pragma unroll
                    for (int k = 0; k < 3; k++) { Fw[k] = t1[k] + t2[k]; Fv[k] = t3[k]; }
                }
            }
        }

        // --- 4. CRBA mass matrix (lower triangle) ---
        float Mm[49];
        {
            float Gc[36];
#pragma unroll
            for (int k = 0; k < 36; k++) Gc[k] = sc.G[NJ - 1][k];
            float Fcw[3], Fcv[3];

            auto gcA = [&](int i) {
                float a0 = sc.A[i][0], a1 = sc.A[i][1], a2 = sc.A[i][2];
                float a3 = sc.A[i][3], a4 = sc.A[i][4], a5 = sc.A[i][5];
#pragma unroll
                for (int r = 0; r < 3; r++) {
                    Fcw[r] = Gc[r * 6 + 0] * a0 + Gc[r * 6 + 1] * a1 + Gc[r * 6 + 2] * a2 +
                             Gc[r * 6 + 3] * a3 + Gc[r * 6 + 4] * a4 + Gc[r * 6 + 5] * a5;
                    Fcv[r] = Gc[(r + 3) * 6 + 0] * a0 + Gc[(r + 3) * 6 + 1] * a1 + Gc[(r + 3) * 6 + 2] * a2 +
                             Gc[(r + 3) * 6 + 3] * a3 + Gc[(r + 3) * 6 + 4] * a4 + Gc[(r + 3) * 6 + 5] * a5;
                }
            };
            auto dotA = [&](int j) {
                return Fcw[0] * sc.A[j][0] + Fcw[1] * sc.A[j][1] + Fcw[2] * sc.A[j][2] +
                       Fcv[0] * sc.A[j][3] + Fcv[1] * sc.A[j][4] + Fcv[2] * sc.A[j][5];
            };
            auto applyT = [&](int jj) {
                float R[9], Q[9];
#pragma unroll
                for (int k = 0; k < 9; k++) { R[k] = SRT(jj, k); Q[k] = SQT(jj, k); }
                float t1[3], t2[3], t3[3];
                mv33_t(R, Fcw, t1);
                mv33_t(Q, Fcv, t2);
                mv33_t(R, Fcv, t3);
#pragma unroll
                for (int k = 0; k < 3; k++) { Fcw[k] = t1[k] + t2[k]; Fcv[k] = t3[k]; }
            };

            gcA(NJ - 1);
            Mm[(NJ - 1) * 7 + (NJ - 1)] = dotA(NJ - 1);
#pragma unroll 1
            for (int j = NJ - 2; j >= 0; j--) {
                applyT(j + 1);
                Mm[(NJ - 1) * 7 + j] = dotA(j);
            }
#pragma unroll 1
            for (int i = NJ - 2; i >= 0; i--) {
                // Gc = AdT_{i+1}^T Gc AdT_{i+1} + G_i   (block form, AdT=[[R,0],[Q,R]])
                {
                    float R[9], Q[9];
#pragma unroll
                    for (int k = 0; k < 9; k++) { R[k] = SRT(i + 1, k); Q[k] = SQT(i + 1, k); }
                    float Ga[9], Gb[9], Gg2[9], Gd[9];
#pragma unroll
                    for (int r = 0; r < 3; r++)
#pragma unroll
                        for (int c = 0; c < 3; c++) {
                            Ga[r * 3 + c] = Gc[r * 6 + c];
                            Gb[r * 3 + c] = Gc[r * 6 + c + 3];
                            Gg2[r * 3 + c] = Gc[(r + 3) * 6 + c];
                            Gd[r * 3 + c] = Gc[(r + 3) * 6 + c + 3];
                        }
                    float P1[9], P2[9], P3[9], P4[9], T1[9], T2[9];
                    mm33(Ga, R, P1);
                    mm33(Gb, Q, T1);
#pragma unroll
                    for (int k = 0; k < 9; k++) P1[k] += T1[k];
                    mm33(Gb, R, P2);
                    mm33(Gg2, R, P3);
                    mm33(Gd, Q, T1);
#pragma unroll
                    for (int k = 0; k < 9; k++) P3[k] += T1[k];
                    mm33(Gd, R, P4);
                    const float* Gi = sc.G[i];
                    mm33_tn(R, P1, T1);
                    mm33_tn(Q, P3, T2);
#pragma unroll
                    for (int r = 0; r < 3; r++)
#pragma unroll
                        for (int c = 0; c < 3; c++) Gc[r * 6 + c] = T1[r * 3 + c] + T2[r * 3 + c] + Gi[r * 6 + c];
                    mm33_tn(R, P2, T1);
                    mm33_tn(Q, P4, T2);
#pragma unroll
                    for (int r = 0; r < 3; r++)
#pragma unroll
                        for (int c = 0; c < 3; c++) Gc[r * 6 + c + 3] = T1[r * 3 + c] + T2[r * 3 + c] + Gi[r * 6 + c + 3];
                    mm33_tn(R, P3, T1);
#pragma unroll
                    for (int r = 0; r < 3; r++)
#pragma unroll
                        for (int c = 0; c < 3; c++) Gc[(r + 3) * 6 + c] = T1[r * 3 + c] + Gi[(r + 3) * 6 + c];
                    mm33_tn(R, P4, T2);
#pragma unroll
                    for (int r = 0; r < 3; r++)
#pragma unroll
                        for (int c = 0; c < 3; c++) Gc[(r + 3) * 6 + c + 3] = T2[r * 3 + c] + Gi[(r + 3) * 6 + c + 3];
                }
                gcA(i);
                Mm[i * 7 + i] = dotA(i);
#pragma unroll 1
                for (int j = i - 1; j >= 0; j--) {
                    applyT(j + 1);
                    Mm[i * 7 + j] = dotA(j);
                }
            }
        }

        // --- 5. Cholesky solve: M dd = tau - h ---
        {
            float rhs[NJ];
#pragma unroll
            for (int i = 0; i < NJ; i++) rhs[i] = tv[i] - hh[i];
#pragma unroll 1
            for (int k2 = 0; k2 < NJ; k2++) {
                float s = Mm[k2 * 7 + k2];
                for (int m2 = 0; m2 < k2; m2++) { float l = Mm[k2 * 7 + m2]; s -= l * l; }
                float inv = 1.f / sqrtf(s);
                Mm[k2 * 7 + k2] = inv;  // store inverse diagonal
                for (int r = k2 + 1; r < NJ; r++) {
                    float s2 = Mm[r * 7 + k2];
                    for (int m2 = 0; m2 < k2; m2++) s2 -= Mm[r * 7 + m2] * Mm[k2 * 7 + m2];
                    Mm[r * 7 + k2] = s2 * inv;
                }
            }
            float y[NJ];
#pragma unroll 1
            for (int i = 0; i < NJ; i++) {
                float s = rhs[i];
                for (int j = 0; j < i; j++) s -= Mm[i * 7 + j] * y[j];
                y[i] = s * Mm[i * 7 + i];
            }
#pragma unroll 1
            for (int i = NJ - 1; i >= 0; i--) {
                float s = y[i];
                for (int j = i + 1; j < NJ; j++) s -= Mm[j * 7 + i] * dd[j];
                dd[i] = s * Mm[i * 7 + i];
            }
        }

        // ===== RK4 combine =====
        float w8 = (st == 0 || st == 3) ? 1.f : 2.f;
#pragma unroll
        for (int i = 0; i < NJ; i++) { aq[i] += w8 * ds[i]; ad[i] += w8 * dd[i]; }
        if (st < 3) {
            float hc = (st == 2) ? DT_C : 0.5f * DT_C;
#pragma unroll
            for (int i = 0; i < NJ; i++) {
                float nq = q0[i] + hc * ds[i];
                float nd = dq0[i] + hc * dd[i];
                qs[i] = nq;
                ds[i] = nd;
            }
        }
    }

    const float PI_F = 3.14159265358979323846f;
    const float TWO_PI = 6.28318530717958647692f;
    float qf2[NJ], dqf[NJ];
#pragma unroll
    for (int i = 0; i < NJ; i++) {
        float vq = q0[i] + (DT_C / 6.f) * aq[i];
        float x = vq + PI_F;
        float r = fmodf(x, TWO_PI);
        if (r < 0.f) r += TWO_PI;
        qf2[i] = r - PI_F;
        float vd = dq0[i] + (DT_C / 6.f) * ad[i];
        dqf[i] = fminf(fmaxf(vd, -MAXV), MAXV);
    }

    // ===== forward kinematics (end-effector x,y) =====
    float Rk[9] = {1.f, 0.f, 0.f, 0.f, 1.f, 0.f, 0.f, 0.f, 1.f};
    float pk[3] = {0.f, 0.f, 0.f};
#pragma unroll 1
    for (int i = 0; i < NJ; i++) {
        float Rm2[9];
        mm33(Rk, sc.MR[i], Rm2);
        float pm2[3];
        mv33(Rk, sc.Mp[i], pm2);
#pragma unroll
        for (int k = 0; k < 3; k++) pm2[k] += pk[k];
        float qi = qf2[i];
        float w[3] = {sc.A[i][0] * qi, sc.A[i][1] * qi, sc.A[i][2] * qi};
        float v[3] = {sc.A[i][3] * qi, sc.A[i][4] * qi, sc.A[i][5] * qi};
        float th = sc.nAw[i] * fabsf(qi);
        float th2 = th * th;
        float a, bb, cc;
        abc_coeffs(th, a, bb, cc);
        float Re[9], Vmx[9];
        rodr(Re, a, bb, w, th2);
        rodr(Vmx, bb, cc, w, th2);
        float pe[3];
        mv33(Vmx, v, pe);
        float Rn[9];
        mm33(Rm2, Re, Rn);
        float pn[3];
        mv33(Rm2, pe, pn);
#pragma unroll
        for (int k = 0; k < 3; k++) pk[k] = pn[k] + pm2[k];
#pragma unroll
        for (int k = 0; k < 9; k++) Rk[k] = Rn[k];
    }
    float pf[3];
    mv33(Rk, sc.Mp[NJ], pf);
    float eex = pf[0] + pk[0];
    float eey = pf[1] + pk[1];

    // ===== outputs: [n,14] state then [n,2] ee, concatenated flat =====
#pragma unroll
    for (int i = 0; i < NJ; i++) {
        out[b * 14 + i] = qf2[i];
        out[b * 14 + 7 + i] = dqf[i];
    }
    out[(size_t)n * 14 + b * 2 + 0] = eex;
    out[(size_t)n * 14 + b * 2 + 1] = eey;
}

extern "C" void kernel_launch(void* const* d_in, const int* in_sizes, int n_in,
                              void* d_out, int out_size) {
    const float* state = (const float*)d_in[0];
    const float* torque = (const float*)d_in[1];
    const float* M = (const float*)d_in[2];
    const float* A = (const float*)d_in[3];
    const float* L = (const float*)d_in[4];
    const float* g = (const float*)d_in[5];
    const float* f = (const float*)d_in[6];
    int n = in_sizes[0] / 14;
    int grid = (n + NT - 1) / NT;
    arm_kernel<<<grid, NT>>>(state, torque, M, A, L, g, f, (float*)d_out, n);
}

// round 10
// speedup vs baseline: 1.2365x; 1.2365x over previous
#include <cuda_runtime.h>
#include <math.h>

#define NT   32
#define NJ   7
#define DT_C 0.1f
#define ACT_R 50.0f
#define MAXV 20.0f

struct SC {
    float A[NJ][6];
    float nAw[NJ];
    float G[NJ][36];
    float MR[NJ + 1][9];
    float Mp[NJ + 1][3];
    float MiR[NJ][9];
    float Mip[NJ][3];
    float AeR[9];
    float AeQ[9];
    float g[3];
    float ftip[6];
};

__device__ __forceinline__ void mm33(const float* A, const float* B, float* C) {
#pragma unroll
    for (int r = 0; r < 3; r++)
#pragma unroll
        for (int c = 0; c < 3; c++)
            C[r * 3 + c] = A[r * 3 + 0] * B[0 * 3 + c] + A[r * 3 + 1] * B[1 * 3 + c] + A[r * 3 + 2] * B[2 * 3 + c];
}
__device__ __forceinline__ void mm33_tn(const float* A, const float* B, float* C) {  // A^T * B
#pragma unroll
    for (int r = 0; r < 3; r++)
#pragma unroll
        for (int c = 0; c < 3; c++)
            C[r * 3 + c] = A[0 * 3 + r] * B[0 * 3 + c] + A[1 * 3 + r] * B[1 * 3 + c] + A[2 * 3 + r] * B[2 * 3 + c];
}
__device__ __forceinline__ void mv33(const float* A, const float* x, float* y) {
#pragma unroll
    for (int r = 0; r < 3; r++) y[r] = A[r * 3 + 0] * x[0] + A[r * 3 + 1] * x[1] + A[r * 3 + 2] * x[2];
}
__device__ __forceinline__ void mv33_t(const float* A, const float* x, float* y) {
#pragma unroll
    for (int r = 0; r < 3; r++) y[r] = A[0 * 3 + r] * x[0] + A[1 * 3 + r] * x[1] + A[2 * 3 + r] * x[2];
}
__device__ __forceinline__ void cross3(const float* a, const float* b, float* c) {
    c[0] = a[1] * b[2] - a[2] * b[1];
    c[1] = a[2] * b[0] - a[0] * b[2];
    c[2] = a[0] * b[1] - a[1] * b[0];
}
// R = I + alpha*K + beta*(w w^T - th2*I), K = skew(w)
__device__ __forceinline__ void rodr(float* R, float a, float b, const float* w, float th2) {
    R[0] = 1.f + b * (w[0] * w[0] - th2);
    R[1] = b * w[0] * w[1] - a * w[2];
    R[2] = b * w[0] * w[2] + a * w[1];
    R[3] = b * w[0] * w[1] + a * w[2];
    R[4] = 1.f + b * (w[1] * w[1] - th2);
    R[5] = b * w[1] * w[2] - a * w[0];
    R[6] = b * w[0] * w[2] - a * w[1];
    R[7] = b * w[1] * w[2] + a * w[0];
    R[8] = 1.f + b * (w[2] * w[2] - th2);
}
__device__ __forceinline__ void abc_coeffs(float th, float& a, float& b, float& c) {
    float th2 = th * th;
    if (th < 1e-4f) {
        a = 1.f - th2 * (1.f / 6.f);
        b = 0.5f - th2 * (1.f / 24.f);
        c = (1.f / 6.f) - th2 * (1.f / 120.f);
    } else {
        float sn = __sinf(th), co = __cosf(th);
        float it = __fdividef(1.f, th);
        a = sn * it;
        b = (1.f - co) * (it * it);
        c = (th - sn) * (it * it * it);
    }
}

__global__ void __launch_bounds__(NT) arm_kernel(
    const float* __restrict__ state, const float* __restrict__ torque,
    const float* __restrict__ Mg, const float* __restrict__ Ag,
    const float* __restrict__ Lg, const float* __restrict__ gg,
    const float* __restrict__ fg, float* __restrict__ out, int n) {
    __shared__ SC sc;
    __shared__ float sRt[NJ * 9 * NT];
    __shared__ float sQt[NJ * 9 * NT];
    __shared__ float sVs[NJ * 6 * NT];
    __shared__ float sVd[NJ * 6 * NT];

    const int tid = threadIdx.x;

#define SRT(i, k) sRt[((i) * 9 + (k)) * NT + tid]
#define SQT(i, k) sQt[((i) * 9 + (k)) * NT + tid]
#define SVS(i, k) sVs[((i) * 6 + (k)) * NT + tid]
#define SVD(i, k) sVd[((i) * 6 + (k)) * NT + tid]

    // ---- block-shared constant preprocessing ----
    for (int idx = tid; idx < NJ * 6; idx += NT) ((float*)sc.A)[idx] = Ag[idx];
    for (int i = tid; i < NJ; i += NT) {
        float a0 = Ag[i * 6], a1 = Ag[i * 6 + 1], a2 = Ag[i * 6 + 2];
        sc.nAw[i] = sqrtf(a0 * a0 + a1 * a1 + a2 * a2);
    }
    for (int idx = tid; idx < NJ * 36; idx += NT) {
        int i = idx / 36, rc = idx % 36, r = rc / 6, cc = rc % 6;
        const float* Lr = Lg + i * 36 + r * 6;
        const float* Lc = Lg + i * 36 + cc * 6;
        float s = 0.f;
#pragma unroll
        for (int k = 0; k < 6; k++) s += Lr[k] * Lc[k];
        sc.G[i][rc] = s;
    }
    for (int i = tid; i < NJ + 1; i += NT) {
        const float* m = Mg + i * 16;
#pragma unroll
        for (int r = 0; r < 3; r++) {
#pragma unroll
            for (int c = 0; c < 3; c++) sc.MR[i][r * 3 + c] = m[r * 4 + c];
            sc.Mp[i][r] = m[r * 4 + 3];
        }
        if (i < NJ) {
#pragma unroll
            for (int r = 0; r < 3; r++) {
#pragma unroll
                for (int c = 0; c < 3; c++) sc.MiR[i][r * 3 + c] = m[c * 4 + r];
                sc.Mip[i][r] = -(m[0 * 4 + r] * m[0 * 4 + 3] + m[1 * 4 + r] * m[1 * 4 + 3] + m[2 * 4 + r] * m[2 * 4 + 3]);
            }
        }
    }
    if (tid == 0) {
        const float* m = Mg + NJ * 16;
        float Re[9], pe[3];
#pragma unroll
        for (int r = 0; r < 3; r++) {
#pragma unroll
            for (int c = 0; c < 3; c++) Re[r * 3 + c] = m[c * 4 + r];
            pe[r] = -(m[0 * 4 + r] * m[0 * 4 + 3] + m[1 * 4 + r] * m[1 * 4 + 3] + m[2 * 4 + r] * m[2 * 4 + 3]);
        }
#pragma unroll
        for (int c = 0; c < 3; c++) {
            sc.AeQ[0 * 3 + c] = -pe[2] * Re[1 * 3 + c] + pe[1] * Re[2 * 3 + c];
            sc.AeQ[1 * 3 + c] = pe[2] * Re[0 * 3 + c] - pe[0] * Re[2 * 3 + c];
            sc.AeQ[2 * 3 + c] = -pe[1] * Re[0 * 3 + c] + pe[0] * Re[1 * 3 + c];
        }
#pragma unroll
        for (int k = 0; k < 9; k++) sc.AeR[k] = Re[k];
#pragma unroll
        for (int k = 0; k < 3; k++) sc.g[k] = gg[k];
#pragma unroll
        for (int k = 0; k < 6; k++) sc.ftip[k] = fg[k];
    }
    __syncthreads();

    const int b = blockIdx.x * NT + tid;
    if (b >= n) return;

    float q0[NJ], dq0[NJ], tv[NJ];
#pragma unroll
    for (int i = 0; i < NJ; i++) {
        q0[i] = state[b * 14 + i];
        dq0[i] = state[b * 14 + 7 + i];
        tv[i] = torque[b * 7 + i] * ACT_R;
    }
    float qs[NJ], ds[NJ], aq[NJ], ad[NJ];
#pragma unroll
    for (int i = 0; i < NJ; i++) { qs[i] = q0[i]; ds[i] = dq0[i]; aq[i] = 0.f; ad[i] = 0.f; }

    float dd[NJ];

#pragma unroll 1
    for (int st = 0; st < 4; ++st) {
        // ===== forward pass: fused adjoint computation + twist/accel recursion =====
        {
            float Vw[3] = {0.f, 0.f, 0.f}, Vv[3] = {0.f, 0.f, 0.f};
            float Dw[3] = {0.f, 0.f, 0.f}, Dv[3] = {-sc.g[0], -sc.g[1], -sc.g[2]};
#pragma unroll
            for (int i = 0; i < NJ; i++) {
                float qi = qs[i];
                float Aw[3] = {sc.A[i][0], sc.A[i][1], sc.A[i][2]};
                float Av[3] = {sc.A[i][3], sc.A[i][4], sc.A[i][5]};
                // --- adjoint AdT_i = Ad( exp(-A_i q_i) * Minv_i ) as (R, Q=skew(p)R), in registers ---
                float w[3] = {-Aw[0] * qi, -Aw[1] * qi, -Aw[2] * qi};
                float v[3] = {-Av[0] * qi, -Av[1] * qi, -Av[2] * qi};
                float th = sc.nAw[i] * fabsf(qi);
                float th2 = th * th;
                float a, bb, cc;
                abc_coeffs(th, a, bb, cc);
                float R0[9], Vmx[9];
                rodr(R0, a, bb, w, th2);
                rodr(Vmx, bb, cc, w, th2);
                float p[3];
                mv33(Vmx, v, p);
                float R[9];
                mm33(R0, sc.MiR[i], R);
                float pm[3];
                mv33(R0, sc.Mip[i], pm);
                float pT[3] = {pm[0] + p[0], pm[1] + p[1], pm[2] + p[2]};
                float Q[9];
#pragma unroll
                for (int c = 0; c < 3; c++) {
                    Q[0 * 3 + c] = -pT[2] * R[1 * 3 + c] + pT[1] * R[2 * 3 + c];
                    Q[1 * 3 + c] = pT[2] * R[0 * 3 + c] - pT[0] * R[2 * 3 + c];
                    Q[2 * 3 + c] = -pT[1] * R[0 * 3 + c] + pT[0] * R[1 * 3 + c];
                }
#pragma unroll
                for (int k = 0; k < 9; k++) { SRT(i, k) = R[k]; SQT(i, k) = Q[k]; }

                // --- twist / accel step, using R,Q from registers ---
                float dqi = ds[i];
                float t1[3], t2[3], t3[3];
                mv33(R, Vw, t1);
                mv33(Q, Vw, t2);
                mv33(R, Vv, t3);
#pragma unroll
                for (int k = 0; k < 3; k++) { Vw[k] = t1[k] + Aw[k] * dqi; Vv[k] = t2[k] + t3[k] + Av[k] * dqi; }
                mv33(R, Dw, t1);
                mv33(Q, Dw, t2);
                mv33(R, Dv, t3);
                float c1[3], c2[3], c3[3];
                cross3(Vw, Aw, c1);
                cross3(Vv, Aw, c2);
                cross3(Vw, Av, c3);
#pragma unroll
                for (int k = 0; k < 3; k++) {
                    Dw[k] = t1[k] + c1[k] * dqi;
                    Dv[k] = t2[k] + t3[k] + (c2[k] + c3[k]) * dqi;
                }
#pragma unroll
                for (int k = 0; k < 3; k++) {
                    SVS(i, k) = Vw[k]; SVS(i, k + 3) = Vv[k];
                    SVD(i, k) = Dw[k]; SVD(i, k + 3) = Dv[k];
                }
            }
        }

        // ===== backward pass: bias forces + CRBA (frame-major seed propagation), fully merged =====
        float rhs[NJ];
        float Mm[49];
        {
            float Sw[NJ][3], Sv[NJ][3];  // live CRBA seeds (registers)
            float Gc[36];
#pragma unroll
            for (int k = 0; k < 36; k++) Gc[k] = sc.G[NJ - 1][k];

            float Fw[3], Fv[3];
            {
                float fw[3] = {sc.ftip[0], sc.ftip[1], sc.ftip[2]};
                float fv[3] = {sc.ftip[3], sc.ftip[4], sc.ftip[5]};
                float t1[3], t2[3], t3[3];
                mv33_t(sc.AeR, fw, t1);
                mv33_t(sc.AeQ, fv, t2);
                mv33_t(sc.AeR, fv, t3);
#pragma unroll
                for (int k = 0; k < 3; k++) { Fw[k] = t1[k] + t2[k]; Fv[k] = t3[k]; }
            }

#pragma unroll
            for (int ii = 0; ii < NJ; ii++) {
                const int i = NJ - 1 - ii;
                const float a0 = sc.A[i][0], a1 = sc.A[i][1], a2 = sc.A[i][2];
                const float a3 = sc.A[i][3], a4 = sc.A[i][4], a5 = sc.A[i][5];

                // new seed S_i = Gc_i * A_i
#pragma unroll
                for (int r = 0; r < 3; r++) {
                    Sw[i][r] = Gc[r * 6 + 0] * a0 + Gc[r * 6 + 1] * a1 + Gc[r * 6 + 2] * a2 +
                               Gc[r * 6 + 3] * a3 + Gc[r * 6 + 4] * a4 + Gc[r * 6 + 5] * a5;
                    Sv[i][r] = Gc[(r + 3) * 6 + 0] * a0 + Gc[(r + 3) * 6 + 1] * a1 + Gc[(r + 3) * 6 + 2] * a2 +
                               Gc[(r + 3) * 6 + 3] * a3 + Gc[(r + 3) * 6 + 4] * a4 + Gc[(r + 3) * 6 + 5] * a5;
                }
                // mass-matrix entries for frame i: Mm[m][i] = S_m . A_i, m >= i
#pragma unroll
                for (int m = 0; m < NJ; m++) {
                    if (m >= i) {
                        Mm[m * 7 + i] = Sw[m][0] * a0 + Sw[m][1] * a1 + Sw[m][2] * a2 +
                                        Sv[m][0] * a3 + Sv[m][1] * a4 + Sv[m][2] * a5;
                    }
                }

                // bias-force accumulation at joint i
                {
                    float vw[3], vv[3], dw[3], dv[3];
#pragma unroll
                    for (int k = 0; k < 3; k++) {
                        vw[k] = SVS(i, k); vv[k] = SVS(i, k + 3);
                        dw[k] = SVD(i, k); dv[k] = SVD(i, k + 3);
                    }
                    const float* Gi = sc.G[i];
                    float GVw[3], GVv[3], GDw[3], GDv[3];
#pragma unroll
                    for (int r = 0; r < 3; r++) {
                        GVw[r] = Gi[r * 6 + 0] * vw[0] + Gi[r * 6 + 1] * vw[1] + Gi[r * 6 + 2] * vw[2] +
                                 Gi[r * 6 + 3] * vv[0] + Gi[r * 6 + 4] * vv[1] + Gi[r * 6 + 5] * vv[2];
                        GVv[r] = Gi[(r + 3) * 6 + 0] * vw[0] + Gi[(r + 3) * 6 + 1] * vw[1] + Gi[(r + 3) * 6 + 2] * vw[2] +
                                 Gi[(r + 3) * 6 + 3] * vv[0] + Gi[(r + 3) * 6 + 4] * vv[1] + Gi[(r + 3) * 6 + 5] * vv[2];
                        GDw[r] = Gi[r * 6 + 0] * dw[0] + Gi[r * 6 + 1] * dw[1] + Gi[r * 6 + 2] * dw[2] +
                                 Gi[r * 6 + 3] * dv[0] + Gi[r * 6 + 4] * dv[1] + Gi[r * 6 + 5] * dv[2];
                        GDv[r] = Gi[(r + 3) * 6 + 0] * dw[0] + Gi[(r + 3) * 6 + 1] * dw[1] + Gi[(r + 3) * 6 + 2] * dw[2] +
                                 Gi[(r + 3) * 6 + 3] * dv[0] + Gi[(r + 3) * 6 + 4] * dv[1] + Gi[(r + 3) * 6 + 5] * dv[2];
                    }
                    float cw[3], cv[3], cx[3];
                    cross3(vw, GVw, cw);
                    cross3(vv, GVv, cv);
                    cross3(vw, GVv, cx);
#pragma unroll
                    for (int k = 0; k < 3; k++) {
                        Fw[k] += GDw[k] + cw[k] + cv[k];
                        Fv[k] += GDv[k] + cx[k];
                    }
                    rhs[i] = tv[i] - (Fw[0] * a0 + Fw[1] * a1 + Fw[2] * a2 +
                                      Fv[0] * a3 + Fv[1] * a4 + Fv[2] * a5);
                }

                if (i > 0) {
                    float R[9], Q[9];
#pragma unroll
                    for (int k = 0; k < 9; k++) { R[k] = SRT(i, k); Q[k] = SQT(i, k); }
                    // push bias force down: F <- AdT_i^T F
                    {
                        float t1[3], t2[3], t3[3];
                        mv33_t(R, Fw, t1);
                        mv33_t(Q, Fv, t2);
                        mv33_t(R, Fv, t3);
#pragma unroll
                        for (int k = 0; k < 3; k++) { Fw[k] = t1[k] + t2[k]; Fv[k] = t3[k]; }
                    }
                    // push all live seeds down (independent chains)
#pragma unroll
                    for (int m = 0; m < NJ; m++) {
                        if (m >= i) {
                            float t1[3], t2[3], t3[3];
                            mv33_t(R, Sw[m], t1);
                            mv33_t(Q, Sv[m], t2);
                            mv33_t(R, Sv[m], t3);
#pragma unroll
                            for (int k = 0; k < 3; k++) { Sw[m][k] = t1[k] + t2[k]; Sv[m][k] = t3[k]; }
                        }
                    }
                    // Gc <- AdT_i^T Gc AdT_i + G_{i-1}
                    {
                        float Ga[9], Gb[9], Gg2[9], Gd[9];
#pragma unroll
                        for (int r = 0; r < 3; r++)
#pragma unroll
                            for (int c = 0; c < 3; c++) {
                                Ga[r * 3 + c] = Gc[r * 6 + c];
                                Gb[r * 3 + c] = Gc[r * 6 + c + 3];
                                Gg2[r * 3 + c] = Gc[(r + 3) * 6 + c];
                                Gd[r * 3 + c] = Gc[(r + 3) * 6 + c + 3];
                            }
                        float P1[9], P2[9], P3[9], P4[9], T1[9], T2[9];
                        mm33(Ga, R, P1);
                        mm33(Gb, Q, T1);
#pragma unroll
                        for (int k = 0; k < 9; k++) P1[k] += T1[k];
                        mm33(Gb, R, P2);
                        mm33(Gg2, R, P3);
                        mm33(Gd, Q, T1);
#pragma unroll
                        for (int k = 0; k < 9; k++) P3[k] += T1[k];
                        mm33(Gd, R, P4);
                        const float* Gi = sc.G[i - 1];
                        mm33_tn(R, P1, T1);
                        mm33_tn(Q, P3, T2);
#pragma unroll
                        for (int r = 0; r < 3; r++)
#pragma unroll
                            for (int c = 0; c < 3; c++) Gc[r * 6 + c] = T1[r * 3 + c] + T2[r * 3 + c] + Gi[r * 6 + c];
                        mm33_tn(R, P2, T1);
                        mm33_tn(Q, P4, T2);
#pragma unroll
                        for (int r = 0; r < 3; r++)
#pragma unroll
                            for (int c = 0; c < 3; c++) Gc[r * 6 + c + 3] = T1[r * 3 + c] + T2[r * 3 + c] + Gi[r * 6 + c + 3];
                        mm33_tn(R, P3, T1);
#pragma unroll
                        for (int r = 0; r < 3; r++)
#pragma unroll
                            for (int c = 0; c < 3; c++) Gc[(r + 3) * 6 + c] = T1[r * 3 + c] + Gi[(r + 3) * 6 + c];
                        mm33_tn(R, P4, T2);
#pragma unroll
                        for (int r = 0; r < 3; r++)
#pragma unroll
                            for (int c = 0; c < 3; c++) Gc[(r + 3) * 6 + c + 3] = T2[r * 3 + c] + Gi[(r + 3) * 6 + c + 3];
                    }
                }
            }
        }

        // ===== Cholesky solve: M dd = rhs (fully unrolled, all-register) =====
        {
#pragma unroll
            for (int k2 = 0; k2 < NJ; k2++) {
                float s = Mm[k2 * 7 + k2];
#pragma unroll
                for (int m2 = 0; m2 < NJ; m2++)
                    if (m2 < k2) { float l = Mm[k2 * 7 + m2]; s -= l * l; }
                float inv = rsqrtf(s);
                Mm[k2 * 7 + k2] = inv;  // store inverse diagonal
#pragma unroll
                for (int r = 0; r < NJ; r++) {
                    if (r > k2) {
                        float s2 = Mm[r * 7 + k2];
#pragma unroll
                        for (int m2 = 0; m2 < NJ; m2++)
                            if (m2 < k2) s2 -= Mm[r * 7 + m2] * Mm[k2 * 7 + m2];
                        Mm[r * 7 + k2] = s2 * inv;
                    }
                }
            }
            float y[NJ];
#pragma unroll
            for (int i = 0; i < NJ; i++) {
                float s = rhs[i];
#pragma unroll
                for (int j = 0; j < NJ; j++)
                    if (j < i) s -= Mm[i * 7 + j] * y[j];
                y[i] = s * Mm[i * 7 + i];
            }
#pragma unroll
            for (int ii = 0; ii < NJ; ii++) {
                const int i = NJ - 1 - ii;
                float s = y[i];
#pragma unroll
                for (int j = 0; j < NJ; j++)
                    if (j > i) s -= Mm[j * 7 + i] * dd[j];
                dd[i] = s * Mm[i * 7 + i];
            }
        }

        // ===== RK4 combine =====
        float w8 = (st == 0 || st == 3) ? 1.f : 2.f;
#pragma unroll
        for (int i = 0; i < NJ; i++) { aq[i] += w8 * ds[i]; ad[i] += w8 * dd[i]; }
        if (st < 3) {
            float hc = (st == 2) ? DT_C : 0.5f * DT_C;
#pragma unroll
            for (int i = 0; i < NJ; i++) {
                qs[i] = q0[i] + hc * ds[i];
                ds[i] = dq0[i] + hc * dd[i];
            }
        }
    }

    const float PI_F = 3.14159265358979323846f;
    const float TWO_PI = 6.28318530717958647692f;
    float qf2[NJ], dqf[NJ];
#pragma unroll
    for (int i = 0; i < NJ; i++) {
        float vq = q0[i] + (DT_C / 6.f) * aq[i];
        float x = vq + PI_F;
        float r = fmodf(x, TWO_PI);
        if (r < 0.f) r += TWO_PI;
        qf2[i] = r - PI_F;
        float vd = dq0[i] + (DT_C / 6.f) * ad[i];
        dqf[i] = fminf(fmaxf(vd, -MAXV), MAXV);
    }

    // ===== forward kinematics (end-effector x,y) =====
    float Rk[9] = {1.f, 0.f, 0.f, 0.f, 1.f, 0.f, 0.f, 0.f, 1.f};
    float pk[3] = {0.f, 0.f, 0.f};
#pragma unroll
    for (int i = 0; i < NJ; i++) {
        float Rm2[9];
        mm33(Rk, sc.MR[i], Rm2);
        float pm2[3];
        mv33(Rk, sc.Mp[i], pm2);
#pragma unroll
        for (int k = 0; k < 3; k++) pm2[k] += pk[k];
        float qi = qf2[i];
        float w[3] = {sc.A[i][0] * qi, sc.A[i][1] * qi, sc.A[i][2] * qi};
        float v[3] = {sc.A[i][3] * qi, sc.A[i][4] * qi, sc.A[i][5] * qi};
        float th = sc.nAw[i] * fabsf(qi);
        float th2 = th * th;
        float a, bb, cc;
        abc_coeffs(th, a, bb, cc);
        float Re[9], Vmx[9];
        rodr(Re, a, bb, w, th2);
        rodr(Vmx, bb, cc, w, th2);
        float pe[3];
        mv33(Vmx, v, pe);
        float Rn[9];
        mm33(Rm2, Re, Rn);
        float pn[3];
        mv33(Rm2, pe, pn);
#pragma unroll
        for (int k = 0; k < 3; k++) pk[k] = pn[k] + pm2[k];
#pragma unroll
        for (int k = 0; k < 9; k++) Rk[k] = Rn[k];
    }
    float pf[3];
    mv33(Rk, sc.Mp[NJ], pf);
    float eex = pf[0] + pk[0];
    float eey = pf[1] + pk[1];

    // ===== outputs: [n,14] state then [n,2] ee, concatenated flat =====
#pragma unroll
    for (int i = 0; i < NJ; i++) {
        out[b * 14 + i] = qf2[i];
        out[b * 14 + 7 + i] = dqf[i];
    }
    out[(size_t)n * 14 + b * 2 + 0] = eex;
    out[(size_t)n * 14 + b * 2 + 1] = eey;
}

extern "C" void kernel_launch(void* const* d_in, const int* in_sizes, int n_in,
                              void* d_out, int out_size) {
    const float* state = (const float*)d_in[0];
    const float* torque = (const float*)d_in[1];
    const float* M = (const float*)d_in[2];
    const float* A = (const float*)d_in[3];
    const float* L = (const float*)d_in[4];
    const float* g = (const float*)d_in[5];
    const float* f = (const float*)d_in[6];
    int n = in_sizes[0] / 14;
    int grid = (n + NT - 1) / NT;
    arm_kernel<<<grid, NT>>>(state, torque, M, A, L, g, f, (float*)d_out, n);
}